// round 7
// baseline (speedup 1.0000x reference)
#include <cuda_runtime.h>
#include <cuda_bf16.h>
#include <cuda_fp16.h>
#include <stdint.h>
#include <math.h>

#define SEQ 4096
#define HID 2048
#define NH  16
#define HD  128

// ---------------- scratch (device globals; no allocation allowed) ----------
__device__ float g_q[SEQ * HID];
__device__ float g_k[SEQ * HID];
__device__ float g_v[SEQ * HID];
__device__ float g_ctx[SEQ * HID];
__device__ __nv_bfloat16 g_xh[SEQ * HID];        // activation hi
__device__ __nv_bfloat16 g_xl[SEQ * HID];        // activation lo
__device__ __nv_bfloat16 g_wh[3 * HID * HID];    // weight^T hi  [N][K] x3
__device__ __nv_bfloat16 g_wl[3 * HID * HID];    // weight^T lo  [N][K] x3

// ---------------- helpers ---------------------------------------------------
__device__ __forceinline__ uint32_t smem_u32(const void* p) {
    uint32_t a;
    asm("{ .reg .u64 t; cvta.to.shared.u64 t, %1; cvt.u32.u64 %0, t; }"
        : "=r"(a) : "l"(p));
    return a;
}
__device__ __forceinline__ void mma_bf16(float c[4], const uint32_t a[4],
                                         const uint32_t b[2]) {
    asm volatile(
        "mma.sync.aligned.m16n8k16.row.col.f32.bf16.bf16.f32 "
        "{%0,%1,%2,%3},{%4,%5,%6,%7},{%8,%9},{%0,%1,%2,%3};"
        : "+f"(c[0]), "+f"(c[1]), "+f"(c[2]), "+f"(c[3])
        : "r"(a[0]), "r"(a[1]), "r"(a[2]), "r"(a[3]), "r"(b[0]), "r"(b[1]));
}
__device__ __forceinline__ void mma_f16(float c[4], const uint32_t a[4],
                                        const uint32_t b[2]) {
    asm volatile(
        "mma.sync.aligned.m16n8k16.row.col.f32.f16.f16.f32 "
        "{%0,%1,%2,%3},{%4,%5,%6,%7},{%8,%9},{%0,%1,%2,%3};"
        : "+f"(c[0]), "+f"(c[1]), "+f"(c[2]), "+f"(c[3])
        : "r"(a[0]), "r"(a[1]), "r"(a[2]), "r"(a[3]), "r"(b[0]), "r"(b[1]));
}
__device__ __forceinline__ void ldsm4(uint32_t r[4], uint32_t addr) {
    asm volatile("ldmatrix.sync.aligned.m8n8.x4.shared.b16 {%0,%1,%2,%3}, [%4];"
                 : "=r"(r[0]), "=r"(r[1]), "=r"(r[2]), "=r"(r[3]) : "r"(addr));
}
__device__ __forceinline__ void ldsm4t(uint32_t r[4], uint32_t addr) {
    asm volatile(
        "ldmatrix.sync.aligned.m8n8.x4.trans.shared.b16 {%0,%1,%2,%3}, [%4];"
        : "=r"(r[0]), "=r"(r[1]), "=r"(r[2]), "=r"(r[3]) : "r"(addr));
}
__device__ __forceinline__ void split2(float x, float y, uint32_t& h, uint32_t& l) {
    __nv_bfloat162 hb = __floats2bfloat162_rn(x, y);
    float hx = __bfloat162float(hb.x), hy = __bfloat162float(hb.y);
    __nv_bfloat162 lb = __floats2bfloat162_rn(x - hx, y - hy);
    h = *(uint32_t*)&hb;
    l = *(uint32_t*)&lb;
}
__device__ __forceinline__ uint32_t pack2h(float x, float y) {
    __half2 p = __floats2half2_rn(x, y);
    return *(uint32_t*)&p;
}

// ---------------- convert: fp32 rows -> bf16 hi/lo --------------------------
__global__ __launch_bounds__(256) void conv_rows(const float* __restrict__ x,
                                                 __nv_bfloat16* __restrict__ h,
                                                 __nv_bfloat16* __restrict__ l,
                                                 int n)
{
    int i = (blockIdx.x * 256 + threadIdx.x) * 4;
    if (i >= n) return;
    float4 v = *(const float4*)(x + i);
    uint32_t h0, l0, h1, l1;
    split2(v.x, v.y, h0, l0);
    split2(v.z, v.w, h1, l1);
    *(uint2*)(h + i) = make_uint2(h0, h1);
    *(uint2*)(l + i) = make_uint2(l0, l1);
}

// ---------------- convert: W[K,N] fp32 -> W^T[N,K] bf16 hi/lo ---------------
__global__ __launch_bounds__(256) void conv_wt(const float* __restrict__ w,
                                               __nv_bfloat16* __restrict__ ht,
                                               __nv_bfloat16* __restrict__ lt)
{
    __shared__ float tile[32][33];
    const int tx = threadIdx.x, ty = threadIdx.y;
    const int n0 = blockIdx.x * 32, k0 = blockIdx.y * 32;
#pragma unroll
    for (int i = 0; i < 4; i++) {
        int k = ty + i * 8;
        tile[k][tx] = w[(size_t)(k0 + k) * HID + n0 + tx];
    }
    __syncthreads();
#pragma unroll
    for (int i = 0; i < 4; i++) {
        int n = ty + i * 8;
        float v = tile[tx][n];
        __nv_bfloat16 hb = __float2bfloat16(v);
        __nv_bfloat16 lb = __float2bfloat16(v - __bfloat162float(hb));
        size_t o = (size_t)(n0 + n) * HID + k0 + tx;
        ht[o] = hb;
        lt[o] = lb;
    }
}

// ---------------- bf16x3 GEMM via mma.sync + ldmatrix -----------------------
// Block 128x128, BK=64, 256 threads = 8 warps (4m x 2n), warp tile 32x64.
// blockIdx.z selects weight slot + output (batched QKV).
#define GAS 72
#define GEMM_SMEM (4 * 128 * GAS * 2)

__global__ __launch_bounds__(256) void gemm_bf16(
    const __nv_bfloat16* __restrict__ Ah_g, const __nv_bfloat16* __restrict__ Al_g,
    const __nv_bfloat16* __restrict__ Bh_g, const __nv_bfloat16* __restrict__ Bl_g,
    float* __restrict__ C0, float* __restrict__ C1, float* __restrict__ C2)
{
    extern __shared__ __nv_bfloat16 sm[];

    const int tid  = threadIdx.x;
    const int warp = tid >> 5;
    const int lane = tid & 31;
    const int g    = lane >> 2;
    const int t    = lane & 3;
    const int wm   = warp >> 1;
    const int wn   = warp & 1;
    const int bx   = blockIdx.x * 128;
    const int by   = blockIdx.y * 128;
    const int z    = blockIdx.z;

    const __nv_bfloat16* Bh_z = Bh_g + (size_t)z * HID * HID;
    const __nv_bfloat16* Bl_z = Bl_g + (size_t)z * HID * HID;
    float* C = (z == 0) ? C0 : (z == 1) ? C1 : C2;

    const uint32_t base = smem_u32(sm);
    const uint32_t aBaseH = base;
    const uint32_t aBaseL = base + 128 * GAS * 2;
    const uint32_t bBaseH = base + 2 * 128 * GAS * 2;
    const uint32_t bBaseL = base + 3 * 128 * GAS * 2;

    float acc[2][8][4] = {};

    const int mat  = lane >> 3;
    const int arow = (lane & 7) + 8 * (mat & 1);
    const int acol8 = 8 * (mat >> 1);
    const int brow = (lane & 7) + 8 * (mat >> 1);
    const int bcol8 = 8 * (mat & 1);

    for (int k0 = 0; k0 < HID; k0 += 64) {
#pragma unroll
        for (int t4 = 0; t4 < 4; t4++) {
            const __nv_bfloat16* src = (t4 == 0) ? Ah_g : (t4 == 1) ? Al_g
                                     : (t4 == 2) ? Bh_z : Bl_z;
            const int rb = (t4 < 2) ? by : bx;
            __nv_bfloat16* dst = sm + t4 * 128 * GAS;
#pragma unroll
            for (int i = 0; i < 4; i++) {
                int v = tid + i * 256;
                int r = v >> 3, cg = v & 7;
                uint4 val = *(const uint4*)(src + (size_t)(rb + r) * HID + k0 + cg * 8);
                *(uint4*)(dst + r * GAS + cg * 8) = val;
            }
        }
        __syncthreads();

#pragma unroll
        for (int kt = 0; kt < 4; kt++) {
            uint32_t a_h[2][4], a_l[2][4];
#pragma unroll
            for (int mt = 0; mt < 2; mt++) {
                uint32_t off = ((wm * 32 + mt * 16 + arow) * GAS + kt * 16 + acol8) * 2;
                ldsm4(a_h[mt], aBaseH + off);
                ldsm4(a_l[mt], aBaseL + off);
            }
            uint32_t b_h[8][2], b_l[8][2];
#pragma unroll
            for (int p = 0; p < 4; p++) {
                uint32_t off = ((wn * 64 + p * 16 + brow) * GAS + kt * 16 + bcol8) * 2;
                uint32_t r4[4];
                ldsm4(r4, bBaseH + off);
                b_h[2 * p][0] = r4[0]; b_h[2 * p][1] = r4[1];
                b_h[2 * p + 1][0] = r4[2]; b_h[2 * p + 1][1] = r4[3];
                ldsm4(r4, bBaseL + off);
                b_l[2 * p][0] = r4[0]; b_l[2 * p][1] = r4[1];
                b_l[2 * p + 1][0] = r4[2]; b_l[2 * p + 1][1] = r4[3];
            }
#pragma unroll
            for (int mt = 0; mt < 2; mt++)
#pragma unroll
                for (int nt = 0; nt < 8; nt++) {
                    mma_bf16(acc[mt][nt], a_h[mt], b_h[nt]);
                    mma_bf16(acc[mt][nt], a_h[mt], b_l[nt]);
                    mma_bf16(acc[mt][nt], a_l[mt], b_h[nt]);
                }
        }
        __syncthreads();
    }

#pragma unroll
    for (int mt = 0; mt < 2; mt++)
#pragma unroll
        for (int nt = 0; nt < 8; nt++) {
            int row = by + wm * 32 + mt * 16 + g;
            int col = bx + wn * 64 + nt * 8 + 2 * t;
            *(float2*)(C + (size_t)row * HID + col) =
                make_float2(acc[mt][nt][0], acc[mt][nt][1]);
            *(float2*)(C + (size_t)(row + 8) * HID + col) =
                make_float2(acc[mt][nt][2], acc[mt][nt][3]);
        }
}

// ---------------- fused per-head RMSNorm + RoPE (in place, Q and K) --------
__global__ __launch_bounds__(256) void rms_rope(float* __restrict__ q,
                                                float* __restrict__ k,
                                                const int* __restrict__ pos,
                                                const float* __restrict__ qw,
                                                const float* __restrict__ kw)
{
    const int s    = blockIdx.x;
    const int warp = threadIdx.x >> 5;
    const int lane = threadIdx.x & 31;
    const float p  = (float)pos[s];

    const int d   = lane * 4;
    const int dp0 = lane * 2;
    const float Cf = 9.210340371976184f / 64.0f;
    float f0 = __expf(-(float)dp0 * Cf);
    float f1 = __expf(-(float)(dp0 + 1) * Cf);
    float s0, c0, s1, c1;
    sincosf(p * f0, &s0, &c0);
    sincosf(p * f1, &s1, &c1);

    float4 w_q = *(const float4*)(qw + d);
    float4 w_k = *(const float4*)(kw + d);

    for (int h = warp; h < NH; h += 8) {
        float* base_q = q + ((size_t)s * NH + h) * HD + d;
        float* base_k = k + ((size_t)s * NH + h) * HD + d;
#pragma unroll
        for (int which = 0; which < 2; which++) {
            float* ptr = which ? base_k : base_q;
            float4 wv  = which ? w_k : w_q;
            float4 x = *(float4*)ptr;
            float ss = x.x * x.x + x.y * x.y + x.z * x.z + x.w * x.w;
#pragma unroll
            for (int off = 16; off; off >>= 1)
                ss += __shfl_xor_sync(0xffffffffu, ss, off);
            float r = rsqrtf(ss * (1.0f / 128.0f) + 1e-6f);
            x.x *= r * wv.x; x.y *= r * wv.y; x.z *= r * wv.z; x.w *= r * wv.w;
            float o0 = x.x * c0 - x.y * s0;
            float o1 = x.x * s0 + x.y * c0;
            float o2 = x.z * c1 - x.w * s1;
            float o3 = x.z * s1 + x.w * c1;
            *(float4*)ptr = make_float4(o0, o1, o2, o3);
        }
    }
}

// ---------------- flash attention via mma.sync ------------------------------
// QK^T: bf16x3 (rel err ~4e-5).  P*V: single fp16 term (fp16 eps 2^-11 ->
// rel err ~2e-4; validated scaling from measured bf16 single-term 1.5e-3).
// CTA: 128 q rows x 64 kv per iter. 8 warps, warp = 16 q rows.
#define FS 136
#define FLASH_SMEM ((2 * 128 * FS + 3 * 64 * FS) * 2)   // 121856 B

__global__ __launch_bounds__(256) void flash_mma(const float* __restrict__ Q,
                                                 const float* __restrict__ K,
                                                 const float* __restrict__ V,
                                                 float* __restrict__ O)
{
    extern __shared__ __nv_bfloat16 sm[];
    __nv_bfloat16* sQh = sm;                    // [128][FS]
    __nv_bfloat16* sQl = sQh + 128 * FS;
    __nv_bfloat16* sKh = sQl + 128 * FS;        // [64][FS]
    __nv_bfloat16* sKl = sKh + 64 * FS;
    __half*        sVh = (__half*)(sKl + 64 * FS);   // [64][FS] fp16

    const int tid  = threadIdx.x;
    const int warp = tid >> 5;
    const int lane = tid & 31;
    const int g    = lane >> 2;
    const int t    = lane & 3;
    const int h    = blockIdx.y;
    const int q0   = blockIdx.x * 128;
    const float scale = 0.08838834764831845f;

    const uint32_t qBaseH = smem_u32(sQh);
    const uint32_t qBaseL = smem_u32(sQl);
    const uint32_t kBaseH = smem_u32(sKh);
    const uint32_t kBaseL = smem_u32(sKl);
    const uint32_t vBase  = smem_u32(sVh);

#pragma unroll
    for (int i = 0; i < 16; i++) {
        int v = tid + i * 256;
        int r = v >> 5, cg = (v & 31) * 4;
        float4 x = *(const float4*)(Q + (size_t)(q0 + r) * HID + h * HD + cg);
        x.x *= scale; x.y *= scale; x.z *= scale; x.w *= scale;
        uint32_t h0, l0, h1, l1;
        split2(x.x, x.y, h0, l0);
        split2(x.z, x.w, h1, l1);
        *(uint2*)(sQh + r * FS + cg) = make_uint2(h0, h1);
        *(uint2*)(sQl + r * FS + cg) = make_uint2(l0, l1);
    }

    const int wq = warp * 16;
    float o[16][4] = {};
    float m0 = -1e30f, m1 = -1e30f, l0s = 0.f, l1s = 0.f;

    const int mat  = lane >> 3;
    const int arow = (lane & 7) + 8 * (mat & 1);
    const int acol8 = 8 * (mat >> 1);
    const int brow = (lane & 7) + 8 * (mat >> 1);
    const int bcol8 = 8 * (mat & 1);
    const int vrow = (lane & 7) + 8 * (mat & 1);
    const int vcol8 = 8 * (mat >> 1);

    for (int kt0 = 0; kt0 < SEQ; kt0 += 64) {
        __syncthreads();
#pragma unroll
        for (int i = 0; i < 8; i++) {
            int v = tid + i * 256;
            int r = v >> 5, cg = (v & 31) * 4;
            size_t goff = (size_t)(kt0 + r) * HID + h * HD + cg;
            float4 xk = *(const float4*)(K + goff);
            uint32_t h0, l0, h1, l1;
            split2(xk.x, xk.y, h0, l0);
            split2(xk.z, xk.w, h1, l1);
            *(uint2*)(sKh + r * FS + cg) = make_uint2(h0, h1);
            *(uint2*)(sKl + r * FS + cg) = make_uint2(l0, l1);
            float4 xv = *(const float4*)(V + goff);
            *(uint2*)(sVh + r * FS + cg) =
                make_uint2(pack2h(xv.x, xv.y), pack2h(xv.z, xv.w));
        }
        __syncthreads();

        // ---- S = Q K^T (bf16x3) ----
        float S[8][4] = {};
#pragma unroll
        for (int c = 0; c < 8; c++) {
            uint32_t a_h[4], a_l[4];
            uint32_t aoff = ((wq + arow) * FS + c * 16 + acol8) * 2;
            ldsm4(a_h, qBaseH + aoff);
            ldsm4(a_l, qBaseL + aoff);
#pragma unroll
            for (int p = 0; p < 4; p++) {
                uint32_t boff = ((p * 16 + brow) * FS + c * 16 + bcol8) * 2;
                uint32_t bh4[4], bl4[4];
                ldsm4(bh4, kBaseH + boff);
                ldsm4(bl4, kBaseL + boff);
                uint32_t bh0[2] = {bh4[0], bh4[1]}, bh1[2] = {bh4[2], bh4[3]};
                uint32_t bl0[2] = {bl4[0], bl4[1]}, bl1[2] = {bl4[2], bl4[3]};
                mma_bf16(S[2 * p], a_h, bh0);
                mma_bf16(S[2 * p], a_h, bl0);
                mma_bf16(S[2 * p], a_l, bh0);
                mma_bf16(S[2 * p + 1], a_h, bh1);
                mma_bf16(S[2 * p + 1], a_h, bl1);
                mma_bf16(S[2 * p + 1], a_l, bh1);
            }
        }

        // ---- online softmax ----
        float rm0 = -1e30f, rm1 = -1e30f;
#pragma unroll
        for (int nt = 0; nt < 8; nt++) {
            rm0 = fmaxf(rm0, fmaxf(S[nt][0], S[nt][1]));
            rm1 = fmaxf(rm1, fmaxf(S[nt][2], S[nt][3]));
        }
        rm0 = fmaxf(rm0, __shfl_xor_sync(0xffffffffu, rm0, 1));
        rm0 = fmaxf(rm0, __shfl_xor_sync(0xffffffffu, rm0, 2));
        rm1 = fmaxf(rm1, __shfl_xor_sync(0xffffffffu, rm1, 1));
        rm1 = fmaxf(rm1, __shfl_xor_sync(0xffffffffu, rm1, 2));
        float mn0 = fmaxf(m0, rm0), mn1 = fmaxf(m1, rm1);
        float a0 = __expf(m0 - mn0), a1 = __expf(m1 - mn1);
        m0 = mn0; m1 = mn1;

        uint32_t Ph0[8], Ph1[8];
        float s0 = 0.f, s1 = 0.f;
#pragma unroll
        for (int nt = 0; nt < 8; nt++) {
            float p00 = __expf(S[nt][0] - mn0);
            float p01 = __expf(S[nt][1] - mn0);
            float p10 = __expf(S[nt][2] - mn1);
            float p11 = __expf(S[nt][3] - mn1);
            s0 += p00 + p01;
            s1 += p10 + p11;
            Ph0[nt] = pack2h(p00, p01);
            Ph1[nt] = pack2h(p10, p11);
        }
        s0 += __shfl_xor_sync(0xffffffffu, s0, 1);
        s0 += __shfl_xor_sync(0xffffffffu, s0, 2);
        s1 += __shfl_xor_sync(0xffffffffu, s1, 1);
        s1 += __shfl_xor_sync(0xffffffffu, s1, 2);
        l0s = l0s * a0 + s0;
        l1s = l1s * a1 + s1;
#pragma unroll
        for (int d = 0; d < 16; d++) {
            o[d][0] *= a0; o[d][1] *= a0;
            o[d][2] *= a1; o[d][3] *= a1;
        }

        // ---- O += P V  (single fp16 term) ----
#pragma unroll
        for (int c = 0; c < 4; c++) {
            uint32_t A_h[4] = {Ph0[2 * c], Ph1[2 * c], Ph0[2 * c + 1], Ph1[2 * c + 1]};
#pragma unroll
            for (int dd = 0; dd < 8; dd++) {
                uint32_t voff = ((c * 16 + vrow) * FS + dd * 16 + vcol8) * 2;
                uint32_t vh4[4];
                ldsm4t(vh4, vBase + voff);
                uint32_t vh0[2] = {vh4[0], vh4[1]}, vh1[2] = {vh4[2], vh4[3]};
                mma_f16(o[2 * dd], A_h, vh0);
                mma_f16(o[2 * dd + 1], A_h, vh1);
            }
        }
    }

    // ---- epilogue ----
    float inv0 = 1.0f / l0s, inv1 = 1.0f / l1s;
    int row0 = q0 + wq + g;
#pragma unroll
    for (int d = 0; d < 16; d++) {
        int col = h * HD + d * 8 + 2 * t;
        *(float2*)(O + (size_t)row0 * HID + col) =
            make_float2(o[d][0] * inv0, o[d][1] * inv0);
        *(float2*)(O + (size_t)(row0 + 8) * HID + col) =
            make_float2(o[d][2] * inv1, o[d][3] * inv1);
    }
}

// ---------------- launch ---------------------------------------------------
extern "C" void kernel_launch(void* const* d_in, const int* in_sizes, int n_in,
                              void* d_out, int out_size)
{
    const float* x   = (const float*)d_in[0];
    const int*   pos = (const int*)d_in[1];
    const float* wq  = (const float*)d_in[2];
    const float* wk  = (const float*)d_in[3];
    const float* wv  = (const float*)d_in[4];
    const float* wo  = (const float*)d_in[5];
    const float* qnw = (const float*)d_in[6];
    const float* knw = (const float*)d_in[7];
    float* out = (float*)d_out;

    float *q, *k, *v, *ctx;
    __nv_bfloat16 *xh, *xl, *wh, *wl;
    cudaGetSymbolAddress((void**)&q,   g_q);
    cudaGetSymbolAddress((void**)&k,   g_k);
    cudaGetSymbolAddress((void**)&v,   g_v);
    cudaGetSymbolAddress((void**)&ctx, g_ctx);
    cudaGetSymbolAddress((void**)&xh,  g_xh);
    cudaGetSymbolAddress((void**)&xl,  g_xl);
    cudaGetSymbolAddress((void**)&wh,  g_wh);
    cudaGetSymbolAddress((void**)&wl,  g_wl);

    cudaFuncSetAttribute(gemm_bf16,
                         cudaFuncAttributeMaxDynamicSharedMemorySize, GEMM_SMEM);
    cudaFuncSetAttribute(flash_mma,
                         cudaFuncAttributeMaxDynamicSharedMemorySize, FLASH_SMEM);

    const int NELEM = SEQ * HID;
    const size_t WSZ = (size_t)HID * HID;
    dim3 cw_grid(HID / 32, HID / 32), cw_blk(32, 8);

    conv_rows<<<NELEM / 1024, 256>>>(x, xh, xl, NELEM);
    conv_wt<<<cw_grid, cw_blk>>>(wq, wh, wl);
    conv_wt<<<cw_grid, cw_blk>>>(wk, wh + WSZ, wl + WSZ);
    conv_wt<<<cw_grid, cw_blk>>>(wv, wh + 2 * WSZ, wl + 2 * WSZ);

    dim3 gg3(HID / 128, SEQ / 128, 3);
    gemm_bf16<<<gg3, 256, GEMM_SMEM>>>(xh, xl, wh, wl, q, k, v);

    rms_rope<<<SEQ, 256>>>(q, k, pos, qnw, knw);

    flash_mma<<<dim3(SEQ / 128, NH), 256, FLASH_SMEM>>>(q, k, v, ctx);

    conv_rows<<<NELEM / 1024, 256>>>(ctx, xh, xl, NELEM);
    conv_wt<<<cw_grid, cw_blk>>>(wo, wh, wl);
    dim3 gg1(HID / 128, SEQ / 128, 1);
    gemm_bf16<<<gg1, 256, GEMM_SMEM>>>(xh, xl, wh, wl, out, out, out);
}

// round 8
// speedup vs baseline: 1.2228x; 1.2228x over previous
#include <cuda_runtime.h>
#include <cuda_bf16.h>
#include <cuda_fp16.h>
#include <stdint.h>
#include <math.h>

#define SEQ 4096
#define HID 2048
#define NH  16
#define HD  128

// ---------------- scratch (device globals; no allocation allowed) ----------
__device__ float g_q[SEQ * HID];
__device__ float g_k[SEQ * HID];
__device__ float g_v[SEQ * HID];
__device__ float g_ctx[SEQ * HID];
__device__ __nv_bfloat16 g_xh[SEQ * HID];        // activation hi
__device__ __nv_bfloat16 g_xl[SEQ * HID];        // activation lo
__device__ __nv_bfloat16 g_wh[3 * HID * HID];    // weight^T hi  [N][K] x3
__device__ __nv_bfloat16 g_wl[3 * HID * HID];    // weight^T lo  [N][K] x3
__device__ __nv_bfloat16 g_qh[SEQ * HID];        // Q (normed, roped, scaled) hi
__device__ __nv_bfloat16 g_ql[SEQ * HID];        // Q lo
__device__ __nv_bfloat16 g_kh[SEQ * HID];        // K hi
__device__ __nv_bfloat16 g_kl[SEQ * HID];        // K lo
__device__ __half        g_vh[SEQ * HID];        // V fp16

// ---------------- helpers ---------------------------------------------------
__device__ __forceinline__ uint32_t smem_u32(const void* p) {
    uint32_t a;
    asm("{ .reg .u64 t; cvta.to.shared.u64 t, %1; cvt.u32.u64 %0, t; }"
        : "=r"(a) : "l"(p));
    return a;
}
__device__ __forceinline__ void mma_bf16(float c[4], const uint32_t a[4],
                                         const uint32_t b[2]) {
    asm volatile(
        "mma.sync.aligned.m16n8k16.row.col.f32.bf16.bf16.f32 "
        "{%0,%1,%2,%3},{%4,%5,%6,%7},{%8,%9},{%0,%1,%2,%3};"
        : "+f"(c[0]), "+f"(c[1]), "+f"(c[2]), "+f"(c[3])
        : "r"(a[0]), "r"(a[1]), "r"(a[2]), "r"(a[3]), "r"(b[0]), "r"(b[1]));
}
__device__ __forceinline__ void mma_f16(float c[4], const uint32_t a[4],
                                        const uint32_t b[2]) {
    asm volatile(
        "mma.sync.aligned.m16n8k16.row.col.f32.f16.f16.f32 "
        "{%0,%1,%2,%3},{%4,%5,%6,%7},{%8,%9},{%0,%1,%2,%3};"
        : "+f"(c[0]), "+f"(c[1]), "+f"(c[2]), "+f"(c[3])
        : "r"(a[0]), "r"(a[1]), "r"(a[2]), "r"(a[3]), "r"(b[0]), "r"(b[1]));
}
__device__ __forceinline__ void ldsm4(uint32_t r[4], uint32_t addr) {
    asm volatile("ldmatrix.sync.aligned.m8n8.x4.shared.b16 {%0,%1,%2,%3}, [%4];"
                 : "=r"(r[0]), "=r"(r[1]), "=r"(r[2]), "=r"(r[3]) : "r"(addr));
}
__device__ __forceinline__ void ldsm4t(uint32_t r[4], uint32_t addr) {
    asm volatile(
        "ldmatrix.sync.aligned.m8n8.x4.trans.shared.b16 {%0,%1,%2,%3}, [%4];"
        : "=r"(r[0]), "=r"(r[1]), "=r"(r[2]), "=r"(r[3]) : "r"(addr));
}
__device__ __forceinline__ void split2(float x, float y, uint32_t& h, uint32_t& l) {
    __nv_bfloat162 hb = __floats2bfloat162_rn(x, y);
    float hx = __bfloat162float(hb.x), hy = __bfloat162float(hb.y);
    __nv_bfloat162 lb = __floats2bfloat162_rn(x - hx, y - hy);
    h = *(uint32_t*)&hb;
    l = *(uint32_t*)&lb;
}
__device__ __forceinline__ uint32_t pack2h(float x, float y) {
    __half2 p = __floats2half2_rn(x, y);
    return *(uint32_t*)&p;
}
__device__ __forceinline__ void cpasync16(uint32_t dst, const void* src) {
    asm volatile("cp.async.cg.shared.global [%0], [%1], 16;"
                 :: "r"(dst), "l"(src) : "memory");
}
#define CP_COMMIT() asm volatile("cp.async.commit_group;" ::: "memory")
#define CP_WAIT(n)  asm volatile("cp.async.wait_group %0;" :: "n"(n) : "memory")

// ---------------- convert: fp32 rows -> bf16 hi/lo --------------------------
__global__ __launch_bounds__(256) void conv_rows(const float* __restrict__ x,
                                                 __nv_bfloat16* __restrict__ h,
                                                 __nv_bfloat16* __restrict__ l,
                                                 int n)
{
    int i = (blockIdx.x * 256 + threadIdx.x) * 4;
    if (i >= n) return;
    float4 v = *(const float4*)(x + i);
    uint32_t h0, l0, h1, l1;
    split2(v.x, v.y, h0, l0);
    split2(v.z, v.w, h1, l1);
    *(uint2*)(h + i) = make_uint2(h0, h1);
    *(uint2*)(l + i) = make_uint2(l0, l1);
}

// ---------------- convert: fp32 -> fp16 -------------------------------------
__global__ __launch_bounds__(256) void conv_h(const float* __restrict__ x,
                                              __half* __restrict__ o, int n)
{
    int i = (blockIdx.x * 256 + threadIdx.x) * 4;
    if (i >= n) return;
    float4 v = *(const float4*)(x + i);
    *(uint2*)(o + i) = make_uint2(pack2h(v.x, v.y), pack2h(v.z, v.w));
}

// ---------------- convert: W[K,N] fp32 -> W^T[N,K] bf16 hi/lo ---------------
__global__ __launch_bounds__(256) void conv_wt(const float* __restrict__ w,
                                               __nv_bfloat16* __restrict__ ht,
                                               __nv_bfloat16* __restrict__ lt)
{
    __shared__ float tile[32][33];
    const int tx = threadIdx.x, ty = threadIdx.y;
    const int n0 = blockIdx.x * 32, k0 = blockIdx.y * 32;
#pragma unroll
    for (int i = 0; i < 4; i++) {
        int k = ty + i * 8;
        tile[k][tx] = w[(size_t)(k0 + k) * HID + n0 + tx];
    }
    __syncthreads();
#pragma unroll
    for (int i = 0; i < 4; i++) {
        int n = ty + i * 8;
        float v = tile[tx][n];
        __nv_bfloat16 hb = __float2bfloat16(v);
        __nv_bfloat16 lb = __float2bfloat16(v - __bfloat162float(hb));
        size_t o = (size_t)(n0 + n) * HID + k0 + tx;
        ht[o] = hb;
        lt[o] = lb;
    }
}

// ---------------- bf16x3 GEMM, cp.async double-buffered ---------------------
// Block 128x128, BK=64, 256 threads = 8 warps (4m x 2n), warp tile 32x64.
#define GAS 72
#define GSTAGE (4 * 128 * GAS)                 // elems per stage
#define GEMM_SMEM (2 * GSTAGE * 2)             // 147456 B

__global__ __launch_bounds__(256) void gemm_bf16(
    const __nv_bfloat16* __restrict__ Ah_g, const __nv_bfloat16* __restrict__ Al_g,
    const __nv_bfloat16* __restrict__ Bh_g, const __nv_bfloat16* __restrict__ Bl_g,
    float* __restrict__ C0, float* __restrict__ C1, float* __restrict__ C2)
{
    extern __shared__ __nv_bfloat16 sm[];

    const int tid  = threadIdx.x;
    const int warp = tid >> 5;
    const int lane = tid & 31;
    const int g    = lane >> 2;
    const int t    = lane & 3;
    const int wm   = warp >> 1;
    const int wn   = warp & 1;
    const int bx   = blockIdx.x * 128;
    const int by   = blockIdx.y * 128;
    const int z    = blockIdx.z;

    const __nv_bfloat16* Bh_z = Bh_g + (size_t)z * HID * HID;
    const __nv_bfloat16* Bl_z = Bl_g + (size_t)z * HID * HID;
    float* C = (z == 0) ? C0 : (z == 1) ? C1 : C2;

    const uint32_t base = smem_u32(sm);

    const int mat  = lane >> 3;
    const int arow = (lane & 7) + 8 * (mat & 1);
    const int acol8 = 8 * (mat >> 1);
    const int brow = (lane & 7) + 8 * (mat >> 1);
    const int bcol8 = 8 * (mat & 1);

    // prefetch helper: stage s, k-offset k0
    auto stage_load = [&](int s, int k0) {
        uint32_t sb = base + (uint32_t)s * GSTAGE * 2;
#pragma unroll
        for (int t4 = 0; t4 < 4; t4++) {
            const __nv_bfloat16* src = (t4 == 0) ? Ah_g : (t4 == 1) ? Al_g
                                     : (t4 == 2) ? Bh_z : Bl_z;
            const int rb = (t4 < 2) ? by : bx;
#pragma unroll
            for (int i = 0; i < 4; i++) {
                int v = tid + i * 256;
                int r = v >> 3, c = v & 7;        // 8x 16B chunks per 128B row
                cpasync16(sb + (uint32_t)(t4 * 128 * GAS + r * GAS) * 2 + c * 16,
                          src + (size_t)(rb + r) * HID + k0 + c * 8);
            }
        }
    };

    float acc[2][8][4] = {};

    stage_load(0, 0);
    CP_COMMIT();

    for (int ch = 0; ch < HID / 64; ch++) {
        if (ch + 1 < HID / 64) {
            stage_load((ch + 1) & 1, (ch + 1) * 64);
            CP_COMMIT();
            CP_WAIT(1);
        } else {
            CP_WAIT(0);
        }
        __syncthreads();

        const uint32_t sb = base + (uint32_t)(ch & 1) * GSTAGE * 2;
        const uint32_t aBaseH = sb;
        const uint32_t aBaseL = sb + 128 * GAS * 2;
        const uint32_t bBaseH = sb + 2 * 128 * GAS * 2;
        const uint32_t bBaseL = sb + 3 * 128 * GAS * 2;

#pragma unroll
        for (int kt = 0; kt < 4; kt++) {
            uint32_t a_h[2][4], a_l[2][4];
#pragma unroll
            for (int mt = 0; mt < 2; mt++) {
                uint32_t off = ((wm * 32 + mt * 16 + arow) * GAS + kt * 16 + acol8) * 2;
                ldsm4(a_h[mt], aBaseH + off);
                ldsm4(a_l[mt], aBaseL + off);
            }
            uint32_t b_h[8][2], b_l[8][2];
#pragma unroll
            for (int p = 0; p < 4; p++) {
                uint32_t off = ((wn * 64 + p * 16 + brow) * GAS + kt * 16 + bcol8) * 2;
                uint32_t r4[4];
                ldsm4(r4, bBaseH + off);
                b_h[2 * p][0] = r4[0]; b_h[2 * p][1] = r4[1];
                b_h[2 * p + 1][0] = r4[2]; b_h[2 * p + 1][1] = r4[3];
                ldsm4(r4, bBaseL + off);
                b_l[2 * p][0] = r4[0]; b_l[2 * p][1] = r4[1];
                b_l[2 * p + 1][0] = r4[2]; b_l[2 * p + 1][1] = r4[3];
            }
#pragma unroll
            for (int mt = 0; mt < 2; mt++)
#pragma unroll
                for (int nt = 0; nt < 8; nt++) {
                    mma_bf16(acc[mt][nt], a_h[mt], b_h[nt]);
                    mma_bf16(acc[mt][nt], a_h[mt], b_l[nt]);
                    mma_bf16(acc[mt][nt], a_l[mt], b_h[nt]);
                }
        }
        __syncthreads();
    }

#pragma unroll
    for (int mt = 0; mt < 2; mt++)
#pragma unroll
        for (int nt = 0; nt < 8; nt++) {
            int row = by + wm * 32 + mt * 16 + g;
            int col = bx + wn * 64 + nt * 8 + 2 * t;
            *(float2*)(C + (size_t)row * HID + col) =
                make_float2(acc[mt][nt][0], acc[mt][nt][1]);
            *(float2*)(C + (size_t)(row + 8) * HID + col) =
                make_float2(acc[mt][nt][2], acc[mt][nt][3]);
        }
}

// ---------------- fused RMSNorm + RoPE -> bf16 hi/lo outputs ----------------
// Reads fp32 q,k (GEMM outputs); writes qh/ql (pre-scaled by 1/sqrt(HD)) and
// kh/kl bf16 hi/lo. No fp32 writeback needed.
__global__ __launch_bounds__(256) void rms_rope(
    const float* __restrict__ q, const float* __restrict__ k,
    const int* __restrict__ pos,
    const float* __restrict__ qw, const float* __restrict__ kw,
    __nv_bfloat16* __restrict__ qh, __nv_bfloat16* __restrict__ ql,
    __nv_bfloat16* __restrict__ kh, __nv_bfloat16* __restrict__ kl)
{
    const int s    = blockIdx.x;
    const int warp = threadIdx.x >> 5;
    const int lane = threadIdx.x & 31;
    const float p  = (float)pos[s];
    const float scale = 0.08838834764831845f;   // 1/sqrt(128)

    const int d   = lane * 4;
    const int dp0 = lane * 2;
    const float Cf = 9.210340371976184f / 64.0f;
    float f0 = __expf(-(float)dp0 * Cf);
    float f1 = __expf(-(float)(dp0 + 1) * Cf);
    float s0, c0, s1, c1;
    sincosf(p * f0, &s0, &c0);
    sincosf(p * f1, &s1, &c1);

    float4 w_q = *(const float4*)(qw + d);
    float4 w_k = *(const float4*)(kw + d);

    for (int h = warp; h < NH; h += 8) {
        size_t off = (size_t)s * HID + h * HD + d;
#pragma unroll
        for (int which = 0; which < 2; which++) {
            const float* ptr = which ? (k + off) : (q + off);
            float4 wv  = which ? w_k : w_q;
            float4 x = *(const float4*)ptr;
            float ss = x.x * x.x + x.y * x.y + x.z * x.z + x.w * x.w;
#pragma unroll
            for (int o2 = 16; o2; o2 >>= 1)
                ss += __shfl_xor_sync(0xffffffffu, ss, o2);
            float r = rsqrtf(ss * (1.0f / 128.0f) + 1e-6f);
            x.x *= r * wv.x; x.y *= r * wv.y; x.z *= r * wv.z; x.w *= r * wv.w;
            float o0 = x.x * c0 - x.y * s0;
            float o1 = x.x * s0 + x.y * c0;
            float o2f = x.z * c1 - x.w * s1;
            float o3 = x.z * s1 + x.w * c1;
            if (!which) { o0 *= scale; o1 *= scale; o2f *= scale; o3 *= scale; }
            uint32_t h0, l0, h1, l1;
            split2(o0, o1, h0, l0);
            split2(o2f, o3, h1, l1);
            if (which) {
                *(uint2*)(kh + off) = make_uint2(h0, h1);
                *(uint2*)(kl + off) = make_uint2(l0, l1);
            } else {
                *(uint2*)(qh + off) = make_uint2(h0, h1);
                *(uint2*)(ql + off) = make_uint2(l0, l1);
            }
        }
    }
}

// ---------------- flash attention, cp.async double-buffered KV ---------------
// QK^T: bf16x3.  PV: single fp16 term.  All operands pre-converted globally.
#define FS 136
#define QBYTES (2 * 128 * FS * 2)              // 69632
#define KVSTAGE (3 * 64 * FS * 2)              // 52224
#define FLASH_SMEM (QBYTES + 2 * KVSTAGE)      // 174080

__global__ __launch_bounds__(256) void flash_mma(
    const __nv_bfloat16* __restrict__ Qh, const __nv_bfloat16* __restrict__ Ql,
    const __nv_bfloat16* __restrict__ Kh, const __nv_bfloat16* __restrict__ Kl,
    const __half* __restrict__ Vh, float* __restrict__ O)
{
    extern __shared__ __nv_bfloat16 sm[];

    const int tid  = threadIdx.x;
    const int warp = tid >> 5;
    const int lane = tid & 31;
    const int g    = lane >> 2;
    const int t    = lane & 3;
    const int h    = blockIdx.y;
    const int q0   = blockIdx.x * 128;

    const uint32_t base   = smem_u32(sm);
    const uint32_t qBaseH = base;
    const uint32_t qBaseL = base + 128 * FS * 2;

    // ---- stage Q hi/lo (plain vector loads, once) ----
#pragma unroll
    for (int i = 0; i < 8; i++) {
        int v = tid + i * 256;
        int r = v >> 4, c = (v & 15) * 8;
        *(uint4*)(sm + r * FS + c) =
            *(const uint4*)(Qh + (size_t)(q0 + r) * HID + h * HD + c);
        *(uint4*)(sm + 128 * FS + r * FS + c) =
            *(const uint4*)(Ql + (size_t)(q0 + r) * HID + h * HD + c);
    }

    // KV prefetch helper
    auto kv_load = [&](int s, int kt0) {
        uint32_t sb = base + QBYTES + (uint32_t)s * KVSTAGE;
#pragma unroll
        for (int t3 = 0; t3 < 3; t3++) {
            const char* src = (t3 == 0) ? (const char*)Kh
                            : (t3 == 1) ? (const char*)Kl : (const char*)Vh;
#pragma unroll
            for (int i = 0; i < 4; i++) {
                int v = tid + i * 256;
                int r = v >> 4, c = v & 15;       // 16x 16B chunks per 256B row
                cpasync16(sb + (uint32_t)(t3 * 64 * FS + r * FS) * 2 + c * 16,
                          src + ((size_t)(kt0 + r) * HID + h * HD) * 2 + c * 16);
            }
        }
    };

    const int wq = warp * 16;
    float o[16][4] = {};
    float m0 = -1e30f, m1 = -1e30f, l0s = 0.f, l1s = 0.f;

    const int mat  = lane >> 3;
    const int arow = (lane & 7) + 8 * (mat & 1);
    const int acol8 = 8 * (mat >> 1);
    const int brow = (lane & 7) + 8 * (mat >> 1);
    const int bcol8 = 8 * (mat & 1);
    const int vrow = (lane & 7) + 8 * (mat & 1);
    const int vcol8 = 8 * (mat >> 1);

    kv_load(0, 0);
    CP_COMMIT();

    for (int it = 0; it < SEQ / 64; it++) {
        if (it + 1 < SEQ / 64) {
            kv_load((it + 1) & 1, (it + 1) * 64);
            CP_COMMIT();
            CP_WAIT(1);
        } else {
            CP_WAIT(0);
        }
        __syncthreads();

        const uint32_t sb = base + QBYTES + (uint32_t)(it & 1) * KVSTAGE;
        const uint32_t kBaseH = sb;
        const uint32_t kBaseL = sb + 64 * FS * 2;
        const uint32_t vBase  = sb + 2 * 64 * FS * 2;

        // ---- S = Q K^T (bf16x3) ----
        float S[8][4] = {};
#pragma unroll
        for (int c = 0; c < 8; c++) {
            uint32_t a_h[4], a_l[4];
            uint32_t aoff = ((wq + arow) * FS + c * 16 + acol8) * 2;
            ldsm4(a_h, qBaseH + aoff);
            ldsm4(a_l, qBaseL + aoff);
#pragma unroll
            for (int p = 0; p < 4; p++) {
                uint32_t boff = ((p * 16 + brow) * FS + c * 16 + bcol8) * 2;
                uint32_t bh4[4], bl4[4];
                ldsm4(bh4, kBaseH + boff);
                ldsm4(bl4, kBaseL + boff);
                uint32_t bh0[2] = {bh4[0], bh4[1]}, bh1[2] = {bh4[2], bh4[3]};
                uint32_t bl0[2] = {bl4[0], bl4[1]}, bl1[2] = {bl4[2], bl4[3]};
                mma_bf16(S[2 * p], a_h, bh0);
                mma_bf16(S[2 * p], a_h, bl0);
                mma_bf16(S[2 * p], a_l, bh0);
                mma_bf16(S[2 * p + 1], a_h, bh1);
                mma_bf16(S[2 * p + 1], a_h, bl1);
                mma_bf16(S[2 * p + 1], a_l, bh1);
            }
        }

        // ---- online softmax ----
        float rm0 = -1e30f, rm1 = -1e30f;
#pragma unroll
        for (int nt = 0; nt < 8; nt++) {
            rm0 = fmaxf(rm0, fmaxf(S[nt][0], S[nt][1]));
            rm1 = fmaxf(rm1, fmaxf(S[nt][2], S[nt][3]));
        }
        rm0 = fmaxf(rm0, __shfl_xor_sync(0xffffffffu, rm0, 1));
        rm0 = fmaxf(rm0, __shfl_xor_sync(0xffffffffu, rm0, 2));
        rm1 = fmaxf(rm1, __shfl_xor_sync(0xffffffffu, rm1, 1));
        rm1 = fmaxf(rm1, __shfl_xor_sync(0xffffffffu, rm1, 2));
        float mn0 = fmaxf(m0, rm0), mn1 = fmaxf(m1, rm1);
        float a0 = __expf(m0 - mn0), a1 = __expf(m1 - mn1);
        m0 = mn0; m1 = mn1;

        uint32_t Ph0[8], Ph1[8];
        float s0 = 0.f, s1 = 0.f;
#pragma unroll
        for (int nt = 0; nt < 8; nt++) {
            float p00 = __expf(S[nt][0] - mn0);
            float p01 = __expf(S[nt][1] - mn0);
            float p10 = __expf(S[nt][2] - mn1);
            float p11 = __expf(S[nt][3] - mn1);
            s0 += p00 + p01;
            s1 += p10 + p11;
            Ph0[nt] = pack2h(p00, p01);
            Ph1[nt] = pack2h(p10, p11);
        }
        s0 += __shfl_xor_sync(0xffffffffu, s0, 1);
        s0 += __shfl_xor_sync(0xffffffffu, s0, 2);
        s1 += __shfl_xor_sync(0xffffffffu, s1, 1);
        s1 += __shfl_xor_sync(0xffffffffu, s1, 2);
        l0s = l0s * a0 + s0;
        l1s = l1s * a1 + s1;
#pragma unroll
        for (int d = 0; d < 16; d++) {
            o[d][0] *= a0; o[d][1] *= a0;
            o[d][2] *= a1; o[d][3] *= a1;
        }

        // ---- O += P V (single fp16 term) ----
#pragma unroll
        for (int c = 0; c < 4; c++) {
            uint32_t A_h[4] = {Ph0[2 * c], Ph1[2 * c], Ph0[2 * c + 1], Ph1[2 * c + 1]};
#pragma unroll
            for (int dd = 0; dd < 8; dd++) {
                uint32_t voff = ((c * 16 + vrow) * FS + dd * 16 + vcol8) * 2;
                uint32_t vh4[4];
                ldsm4t(vh4, vBase + voff);
                uint32_t vh0[2] = {vh4[0], vh4[1]}, vh1[2] = {vh4[2], vh4[3]};
                mma_f16(o[2 * dd], A_h, vh0);
                mma_f16(o[2 * dd + 1], A_h, vh1);
            }
        }
        __syncthreads();
    }

    // ---- epilogue ----
    float inv0 = 1.0f / l0s, inv1 = 1.0f / l1s;
    int row0 = q0 + wq + g;
#pragma unroll
    for (int d = 0; d < 16; d++) {
        int col = h * HD + d * 8 + 2 * t;
        *(float2*)(O + (size_t)row0 * HID + col) =
            make_float2(o[d][0] * inv0, o[d][1] * inv0);
        *(float2*)(O + (size_t)(row0 + 8) * HID + col) =
            make_float2(o[d][2] * inv1, o[d][3] * inv1);
    }
}

// ---------------- launch ---------------------------------------------------
extern "C" void kernel_launch(void* const* d_in, const int* in_sizes, int n_in,
                              void* d_out, int out_size)
{
    const float* x   = (const float*)d_in[0];
    const int*   pos = (const int*)d_in[1];
    const float* wq  = (const float*)d_in[2];
    const float* wk  = (const float*)d_in[3];
    const float* wv  = (const float*)d_in[4];
    const float* wo  = (const float*)d_in[5];
    const float* qnw = (const float*)d_in[6];
    const float* knw = (const float*)d_in[7];
    float* out = (float*)d_out;

    float *q, *k, *v, *ctx;
    __nv_bfloat16 *xh, *xl, *wh, *wl, *qh, *ql, *kh, *kl;
    __half *vh;
    cudaGetSymbolAddress((void**)&q,   g_q);
    cudaGetSymbolAddress((void**)&k,   g_k);
    cudaGetSymbolAddress((void**)&v,   g_v);
    cudaGetSymbolAddress((void**)&ctx, g_ctx);
    cudaGetSymbolAddress((void**)&xh,  g_xh);
    cudaGetSymbolAddress((void**)&xl,  g_xl);
    cudaGetSymbolAddress((void**)&wh,  g_wh);
    cudaGetSymbolAddress((void**)&wl,  g_wl);
    cudaGetSymbolAddress((void**)&qh,  g_qh);
    cudaGetSymbolAddress((void**)&ql,  g_ql);
    cudaGetSymbolAddress((void**)&kh,  g_kh);
    cudaGetSymbolAddress((void**)&kl,  g_kl);
    cudaGetSymbolAddress((void**)&vh,  g_vh);

    cudaFuncSetAttribute(gemm_bf16,
                         cudaFuncAttributeMaxDynamicSharedMemorySize, GEMM_SMEM);
    cudaFuncSetAttribute(flash_mma,
                         cudaFuncAttributeMaxDynamicSharedMemorySize, FLASH_SMEM);

    const int NELEM = SEQ * HID;
    const size_t WSZ = (size_t)HID * HID;
    dim3 cw_grid(HID / 32, HID / 32), cw_blk(32, 8);

    conv_rows<<<NELEM / 1024, 256>>>(x, xh, xl, NELEM);
    conv_wt<<<cw_grid, cw_blk>>>(wq, wh, wl);
    conv_wt<<<cw_grid, cw_blk>>>(wk, wh + WSZ, wl + WSZ);
    conv_wt<<<cw_grid, cw_blk>>>(wv, wh + 2 * WSZ, wl + 2 * WSZ);

    dim3 gg3(HID / 128, SEQ / 128, 3);
    gemm_bf16<<<gg3, 256, GEMM_SMEM>>>(xh, xl, wh, wl, q, k, v);

    rms_rope<<<SEQ, 256>>>(q, k, pos, qnw, knw, qh, ql, kh, kl);
    conv_h<<<NELEM / 1024, 256>>>(v, vh, NELEM);

    flash_mma<<<dim3(SEQ / 128, NH), 256, FLASH_SMEM>>>(qh, ql, kh, kl, vh, ctx);

    conv_rows<<<NELEM / 1024, 256>>>(ctx, xh, xl, NELEM);
    conv_wt<<<cw_grid, cw_blk>>>(wo, wh, wl);
    dim3 gg1(HID / 128, SEQ / 128, 1);
    gemm_bf16<<<gg1, 256, GEMM_SMEM>>>(xh, xl, wh, wl, out, out, out);
}